// round 4
// baseline (speedup 1.0000x reference)
#include <cuda_runtime.h>

// IF spiking neuron forward, T=4. R4: minimal-register variant of the
// batch-in-thread kernel. No prefetch double-buffer, no spike store buffer
// (store immediately), plain loads/stores (no .cs hints — match R1's memory
// path), __launch_bounds__(256,6) to hold >=6 blocks/SM (75% occupancy).
// Params still read exactly once per feature (~775 MB total DRAM traffic).

#ifndef T_STEPS
#define T_STEPS 4
#endif

__global__ __launch_bounds__(256, 6) void if_fwd_kernel(
    const float4* __restrict__ x,      // [T, B, N4]
    const float4* __restrict__ thre,   // [N4]
    const float4* __restrict__ dtm,    // [N4]
    float4* __restrict__ out,          // [T, B, N4]
    long long N4,
    int B)
{
    long long f = (long long)blockIdx.x * blockDim.x + threadIdx.x;
    if (f >= N4) return;

    const float4 th = thre[f];
    float4 m0 = dtm[f];
    m0.x *= th.x; m0.y *= th.y; m0.z *= th.z; m0.w *= th.w;

    const float4* xp = x + f;
    float4* op = out + f;
    const long long tstride = (long long)B * N4;

#pragma unroll 1
    for (int b = 0; b < B; b++) {
        // 4 independent loads; ptxas front-batches them (no explicit buffer
        // needed, keeps register count down).
        float4 xv0 = xp[0 * tstride];
        float4 xv1 = xp[1 * tstride];
        float4 xv2 = xp[2 * tstride];
        float4 xv3 = xp[3 * tstride];

        float4 mem = m0;
        float4 s;

        // t = 0
        mem.x += xv0.x; mem.y += xv0.y; mem.z += xv0.z; mem.w += xv0.w;
        s.x = (mem.x >= th.x) ? th.x : 0.0f;
        s.y = (mem.y >= th.y) ? th.y : 0.0f;
        s.z = (mem.z >= th.z) ? th.z : 0.0f;
        s.w = (mem.w >= th.w) ? th.w : 0.0f;
        op[0 * tstride] = s;
        mem.x -= s.x; mem.y -= s.y; mem.z -= s.z; mem.w -= s.w;

        // t = 1
        mem.x += xv1.x; mem.y += xv1.y; mem.z += xv1.z; mem.w += xv1.w;
        s.x = (mem.x >= th.x) ? th.x : 0.0f;
        s.y = (mem.y >= th.y) ? th.y : 0.0f;
        s.z = (mem.z >= th.z) ? th.z : 0.0f;
        s.w = (mem.w >= th.w) ? th.w : 0.0f;
        op[1 * tstride] = s;
        mem.x -= s.x; mem.y -= s.y; mem.z -= s.z; mem.w -= s.w;

        // t = 2
        mem.x += xv2.x; mem.y += xv2.y; mem.z += xv2.z; mem.w += xv2.w;
        s.x = (mem.x >= th.x) ? th.x : 0.0f;
        s.y = (mem.y >= th.y) ? th.y : 0.0f;
        s.z = (mem.z >= th.z) ? th.z : 0.0f;
        s.w = (mem.w >= th.w) ? th.w : 0.0f;
        op[2 * tstride] = s;
        mem.x -= s.x; mem.y -= s.y; mem.z -= s.z; mem.w -= s.w;

        // t = 3 (no need to update mem afterwards)
        mem.x += xv3.x; mem.y += xv3.y; mem.z += xv3.z; mem.w += xv3.w;
        s.x = (mem.x >= th.x) ? th.x : 0.0f;
        s.y = (mem.y >= th.y) ? th.y : 0.0f;
        s.z = (mem.z >= th.z) ? th.z : 0.0f;
        s.w = (mem.w >= th.w) ? th.w : 0.0f;
        op[3 * tstride] = s;

        xp += N4;
        op += N4;
    }
}

extern "C" void kernel_launch(void* const* d_in, const int* in_sizes, int n_in,
                              void* d_out, int out_size)
{
    const float* x   = (const float*)d_in[0];
    const float* th  = (const float*)d_in[1];
    const float* dtm = (const float*)d_in[2];
    float* out = (float*)d_out;

    const long long N = in_sizes[1];                   // 1024*3072
    const int B = (int)(in_sizes[0] / (T_STEPS * N));  // 8
    const long long N4 = N / 4;

    const int threads = 256;
    dim3 grid((unsigned)((N4 + threads - 1) / threads));

    if_fwd_kernel<<<grid, threads>>>(
        (const float4*)x, (const float4*)th, (const float4*)dtm,
        (float4*)out, N4, B);
}